// round 3
// baseline (speedup 1.0000x reference)
#include <cuda_runtime.h>
#include <stdint.h>

// fx, fy : float32 [B=16, C=128, D=3, N=4096], topk=4 -> k=1024
// Output: concat(fx_sel, fy_sel), each [16,128,3,1024] float32.

#define B_ 16
#define C_ 128
#define D_ 3
#define N_ 4096
#define K_ 1024
#define BN_ (B_ * N_)

#define BATCH_STRIDE  ((long long)C_ * D_ * N_)       // 1,572,864
#define C_STRIDE      (D_ * N_)                       // 12,288
#define HALF_OUT      ((long long)B_ * C_ * D_ * K_)  // 6,291,456

#define NCHUNK 4
#define CPC    (C_ / NCHUNK)   // 32 c per chunk

// Scratch (__device__ globals: allocation-free rule)
__device__ double g_mean[6 * BN_];   // [z=tensor*3+d][b][n]
__device__ double g_pq[6 * BN_];     // normalized fx_par/fy_par, same layout
__device__ double g_part[NCHUNK * BN_];
__device__ int    g_idx[B_ * K_];

// ---------------------------------------------------------------------------
// Kernel 1: means. One thread per (tensor,d,b,n) -> 393k threads.
// Single fp64 accumulator group; loads batch deeply (DRAM-bound).
// ---------------------------------------------------------------------------
__global__ __launch_bounds__(256)
void mean_kernel(const float* __restrict__ fx, const float* __restrict__ fy,
                 double* __restrict__ mean)
{
    int n = blockIdx.x * 256 + threadIdx.x;
    int b = blockIdx.y;
    int z = blockIdx.z;                       // 0..5: tensor*3 + d
    const float* src = (z < 3 ? fx : fy)
                     + (long long)b * BATCH_STRIDE + (long long)(z % 3) * N_ + n;

    double a0 = 0, a1 = 0, a2 = 0, a3 = 0;
#pragma unroll 4
    for (int c = 0; c < C_; c += 4) {
        a0 += (double)src[(c + 0) * C_STRIDE];
        a1 += (double)src[(c + 1) * C_STRIDE];
        a2 += (double)src[(c + 2) * C_STRIDE];
        a3 += (double)src[(c + 3) * C_STRIDE];
    }
    mean[(long long)z * BN_ + b * N_ + n] = ((a0 + a1) + (a2 + a3)) * (1.0 / C_);
}

// ---------------------------------------------------------------------------
// Kernel 2: normalize means -> p (fx_par), q (fy_par). 65536 threads, trivial.
// ---------------------------------------------------------------------------
__global__ __launch_bounds__(256)
void norm_kernel(const double* __restrict__ mean, double* __restrict__ pq)
{
    int i = blockIdx.x * 256 + threadIdx.x;   // b*N + n
    double x0 = mean[i];
    double x1 = mean[BN_ + i];
    double x2 = mean[2 * BN_ + i];
    double y0 = mean[3 * BN_ + i];
    double y1 = mean[4 * BN_ + i];
    double y2 = mean[5 * BN_ + i];

    double nx = sqrt(x0 * x0 + x1 * x1 + x2 * x2) + 1e-6;
    double ny = sqrt(y0 * y0 + y1 * y1 + y2 * y2) + 1e-6;

    pq[i]           = x0 / nx;
    pq[BN_ + i]     = x1 / nx;
    pq[2 * BN_ + i] = x2 / nx;
    pq[3 * BN_ + i] = y0 / ny;
    pq[4 * BN_ + i] = y1 / ny;
    pq[5 * BN_ + i] = y2 / ny;
}

// ---------------------------------------------------------------------------
// Kernel 3: partial scores. Thread per (b,n,chunk); 262k threads.
// acc += (x . p)(y . q) over 32 c's. One accumulator chain -> deep MLP.
// ---------------------------------------------------------------------------
__global__ __launch_bounds__(256)
void score_kernel(const float* __restrict__ fx, const float* __restrict__ fy,
                  const double* __restrict__ pq, double* __restrict__ part)
{
    int n  = blockIdx.x * 256 + threadIdx.x;
    int b  = blockIdx.y;
    int ch = blockIdx.z;
    int i  = b * N_ + n;

    double p0 = pq[i];
    double p1 = pq[BN_ + i];
    double p2 = pq[2 * BN_ + i];
    double q0 = pq[3 * BN_ + i];
    double q1 = pq[4 * BN_ + i];
    double q2 = pq[5 * BN_ + i];

    const float* px = fx + (long long)b * BATCH_STRIDE
                    + (long long)ch * CPC * C_STRIDE + n;
    const float* py = fy + (long long)b * BATCH_STRIDE
                    + (long long)ch * CPC * C_STRIDE + n;

    double a0 = 0, a1 = 0;
#pragma unroll 4
    for (int c = 0; c < CPC; c++) {
        const float* rx = px + c * C_STRIDE;
        const float* ry = py + c * C_STRIDE;
        float x0 = rx[0], x1 = rx[N_], x2 = rx[2 * N_];
        float y0 = ry[0], y1 = ry[N_], y2 = ry[2 * N_];

        double dx = fma((double)x2, p2, fma((double)x1, p1, (double)x0 * p0));
        double dy = fma((double)y2, q2, fma((double)y1, q1, (double)y0 * q0));
        if (c & 1) a1 = fma(dx, dy, a1);
        else       a0 = fma(dx, dy, a0);
    }
    part[(long long)ch * BN_ + i] = a0 + a1;
}

// ---------------------------------------------------------------------------
// Kernel 4: sum partials -> sortable key -> per-batch bitonic sort (smem),
// emit top-1024 indices in rank order (tie: ascending index, like lax.top_k).
// ---------------------------------------------------------------------------
__global__ __launch_bounds__(1024)
void topk_kernel(const double* __restrict__ part, int* __restrict__ idxout)
{
    __shared__ unsigned long long keys[N_];
    int b = blockIdx.x;
    int tid = threadIdx.x;

#pragma unroll
    for (int it = 0; it < 4; it++) {
        int n = tid + it * 1024;
        int i = b * N_ + n;
        double s = (part[i] + part[BN_ + i])
                 + (part[2 * BN_ + i] + part[3 * BN_ + i]);
        unsigned long long u = (unsigned long long)__double_as_longlong(s);
        if (u & 0x8000000000000000ULL) u = ~u;
        else                           u |= 0x8000000000000000ULL;
        keys[n] = (u & ~0xFFFULL) | (unsigned long long)(N_ - 1 - n);
    }
    __syncthreads();

    for (int k = 2; k <= N_; k <<= 1) {
        for (int j = k >> 1; j > 0; j >>= 1) {
#pragma unroll
            for (int it = 0; it < 4; it++) {
                int t = tid + it * 1024;
                int ixj = t ^ j;
                if (ixj > t) {
                    unsigned long long a = keys[t];
                    unsigned long long c = keys[ixj];
                    bool desc = ((t & k) == 0);
                    if (desc ? (a < c) : (a > c)) {
                        keys[t] = c;
                        keys[ixj] = a;
                    }
                }
            }
            __syncthreads();
        }
    }

    idxout[b * K_ + tid] = (N_ - 1) - (int)(keys[tid] & 0xFFFULL);
}

// ---------------------------------------------------------------------------
// Kernel 5: gather selected columns. One thread per output element.
// ---------------------------------------------------------------------------
__global__ __launch_bounds__(256)
void gather_kernel(const float* __restrict__ fx, const float* __restrict__ fy,
                   const int* __restrict__ idx, float* __restrict__ out)
{
    long long t = (long long)blockIdx.x * blockDim.x + threadIdx.x;
    if (t >= 2 * HALF_OUT) return;

    const float* src = fx;
    float* dst = out;
    long long tt = t;
    if (tt >= HALF_OUT) {
        tt -= HALF_OUT;
        src = fy;
        dst = out + HALF_OUT;
    }

    int j = (int)(tt & (K_ - 1));
    long long rest = tt >> 10;          // (b*C + c)*D + d
    int d = (int)(rest % D_);
    long long bc = rest / D_;           // b*C + c
    int b = (int)(bc >> 7);

    int n = idx[b * K_ + j];
    dst[tt] = src[bc * (long long)C_STRIDE + (long long)d * N_ + n];
}

// ---------------------------------------------------------------------------
extern "C" void kernel_launch(void* const* d_in, const int* in_sizes, int n_in,
                              void* d_out, int out_size)
{
    const float* fx = (const float*)d_in[0];
    const float* fy = (const float*)d_in[1];
    float* out = (float*)d_out;

    double *mean, *pq, *part;
    int *idx;
    cudaGetSymbolAddress((void**)&mean, g_mean);
    cudaGetSymbolAddress((void**)&pq,   g_pq);
    cudaGetSymbolAddress((void**)&part, g_part);
    cudaGetSymbolAddress((void**)&idx,  g_idx);

    dim3 g1(N_ / 256, B_, 6);
    mean_kernel<<<g1, 256>>>(fx, fy, mean);

    norm_kernel<<<BN_ / 256, 256>>>(mean, pq);

    dim3 g3(N_ / 256, B_, NCHUNK);
    score_kernel<<<g3, 256>>>(fx, fy, pq, part);

    topk_kernel<<<B_, 1024>>>(part, idx);

    long long total = 2 * HALF_OUT;
    int blocks = (int)((total + 255) / 256);
    gather_kernel<<<blocks, 256>>>(fx, fy, idx, out);
}

// round 4
// speedup vs baseline: 2.3678x; 2.3678x over previous
#include <cuda_runtime.h>
#include <stdint.h>

// fx, fy : float32 [B=16, C=128, D=3, N=4096], topk=4 -> k=1024
// Output: concat(fx_sel, fy_sel), each [16,128,3,1024] float32.

#define B_ 16
#define C_ 128
#define D_ 3
#define N_ 4096
#define K_ 1024
#define BN_ (B_ * N_)

#define BATCH_STRIDE  ((long long)C_ * D_ * N_)       // 1,572,864
#define C_STRIDE      (D_ * N_)                       // 12,288
#define HALF_OUT      ((long long)B_ * C_ * D_ * K_)  // 6,291,456

#define NCHUNK 4
#define CPC    (C_ / NCHUNK)   // 32

// Scratch (__device__ globals: allocation-free rule)
__device__ float2 g_mean[6 * BN_];   // (hi, lo) compensated sums, [z][b][n]
__device__ float2 g_pq[6 * BN_];     // p,q as double-single, [z][b][n]
__device__ float2 g_part[NCHUNK * BN_];
__device__ int    g_idx[B_ * K_];

// ---- error-free fp32 transforms (fma pipe; no fp64) ------------------------
__device__ __forceinline__ float2 two_sum(float a, float b) {
    float s  = a + b;
    float bb = s - a;
    float e  = (a - (s - bb)) + (b - bb);
    return make_float2(s, e);
}
__device__ __forceinline__ float2 two_prod(float a, float b) {
    float p = a * b;
    float e = fmaf(a, b, -p);
    return make_float2(p, e);
}

// ---------------------------------------------------------------------------
// Kernel 1: compensated means. Thread per (z,b,n); z = tensor*3 + d.
// Two interleaved Neumaier accumulators for ILP; exact combine at end.
// ---------------------------------------------------------------------------
__global__ __launch_bounds__(256)
void mean_kernel(const float* __restrict__ fx, const float* __restrict__ fy,
                 float2* __restrict__ mean)
{
    int n = blockIdx.x * 256 + threadIdx.x;
    int b = blockIdx.y;
    int z = blockIdx.z;
    const float* src = (z < 3 ? fx : fy)
                     + (long long)b * BATCH_STRIDE + (long long)(z % 3) * N_ + n;

    float s0 = 0.f, c0 = 0.f, s1 = 0.f, c1 = 0.f;
#pragma unroll 4
    for (int c = 0; c < C_; c += 2) {
        float v0 = src[c * C_STRIDE];
        float v1 = src[(c + 1) * C_STRIDE];
        float2 t0 = two_sum(s0, v0); s0 = t0.x; c0 += t0.y;
        float2 t1 = two_sum(s1, v1); s1 = t1.x; c1 += t1.y;
    }
    float2 t = two_sum(s0, s1);
    mean[(long long)z * BN_ + b * N_ + n] = make_float2(t.x, (c0 + c1) + t.y);
}

// ---------------------------------------------------------------------------
// Kernel 2: normalize (tiny fp64 usage: 65k threads, ~30 ops each).
// Emits p (fx_par) and q (fy_par) as double-single float2.
// ---------------------------------------------------------------------------
__global__ __launch_bounds__(256)
void norm_kernel(const float2* __restrict__ mean, float2* __restrict__ pq)
{
    int i = blockIdx.x * 256 + threadIdx.x;   // b*N + n

    double m[6];
#pragma unroll
    for (int z = 0; z < 6; z++) {
        float2 v = mean[(long long)z * BN_ + i];
        m[z] = ((double)v.x + (double)v.y) * (1.0 / C_);
    }
    double nx = sqrt(m[0]*m[0] + m[1]*m[1] + m[2]*m[2]) + 1e-6;
    double ny = sqrt(m[3]*m[3] + m[4]*m[4] + m[5]*m[5]) + 1e-6;

#pragma unroll
    for (int z = 0; z < 6; z++) {
        double v = m[z] / (z < 3 ? nx : ny);
        float hi = (float)v;
        float lo = (float)(v - (double)hi);
        pq[(long long)z * BN_ + i] = make_float2(hi, lo);
    }
}

// ---------------------------------------------------------------------------
// Kernel 3: partial scores, all compensated fp32.
// acc(df) += (x·p)(df) * (y·q)(df) over 32 c's per chunk.
// ---------------------------------------------------------------------------
__global__ __launch_bounds__(256)
void score_kernel(const float* __restrict__ fx, const float* __restrict__ fy,
                  const float2* __restrict__ pq, float2* __restrict__ part)
{
    int n  = blockIdx.x * 256 + threadIdx.x;
    int b  = blockIdx.y;
    int ch = blockIdx.z;
    int i  = b * N_ + n;

    float2 P0 = pq[i];
    float2 P1 = pq[BN_ + i];
    float2 P2 = pq[2 * BN_ + i];
    float2 Q0 = pq[3 * BN_ + i];
    float2 Q1 = pq[4 * BN_ + i];
    float2 Q2 = pq[5 * BN_ + i];

    const float* px = fx + (long long)b * BATCH_STRIDE
                    + (long long)ch * CPC * C_STRIDE + n;
    const float* py = fy + (long long)b * BATCH_STRIDE
                    + (long long)ch * CPC * C_STRIDE + n;

    float sh = 0.f, sl = 0.f;
#pragma unroll 4
    for (int c = 0; c < CPC; c++) {
        const float* rx = px + c * C_STRIDE;
        const float* ry = py + c * C_STRIDE;
        float x0 = rx[0], x1 = rx[N_], x2 = rx[2 * N_];
        float y0 = ry[0], y1 = ry[N_], y2 = ry[2 * N_];

        // dx = x . p (compensated)
        float2 t = two_prod(x0, P0.x);
        float dxh = t.x;
        float dxl = fmaf(x0, P0.y, t.y);
        t = two_prod(x1, P1.x);
        float2 s = two_sum(dxh, t.x);
        dxh = s.x; dxl += s.y + fmaf(x1, P1.y, t.y);
        t = two_prod(x2, P2.x);
        s = two_sum(dxh, t.x);
        dxh = s.x; dxl += s.y + fmaf(x2, P2.y, t.y);

        // dy = y . q (compensated)
        t = two_prod(y0, Q0.x);
        float dyh = t.x;
        float dyl = fmaf(y0, Q0.y, t.y);
        t = two_prod(y1, Q1.x);
        s = two_sum(dyh, t.x);
        dyh = s.x; dyl += s.y + fmaf(y1, Q1.y, t.y);
        t = two_prod(y2, Q2.x);
        s = two_sum(dyh, t.x);
        dyh = s.x; dyl += s.y + fmaf(y2, Q2.y, t.y);

        // acc += dx * dy (compensated)
        float2 pp = two_prod(dxh, dyh);
        float pe = fmaf(dxh, dyl, fmaf(dxl, dyh, pp.y));
        float2 a = two_sum(sh, pp.x);
        sh = a.x; sl += a.y + pe;
    }
    part[(long long)ch * BN_ + i] = make_float2(sh, sl);
}

// ---------------------------------------------------------------------------
// Kernel 4: combine partials (fp64, trivial count) -> u64 key -> bitonic.
// j<=2 levels run in registers (thread owns 4 contiguous elements).
// ---------------------------------------------------------------------------
__global__ __launch_bounds__(1024)
void topk_kernel(const float2* __restrict__ part, int* __restrict__ idxout)
{
    __shared__ unsigned long long keys[N_];
    int b = blockIdx.x;
    int tid = threadIdx.x;

#pragma unroll
    for (int it = 0; it < 4; it++) {
        int n = tid + it * 1024;
        int i = b * N_ + n;
        double ssum = 0.0;
#pragma unroll
        for (int ch = 0; ch < NCHUNK; ch++) {
            float2 v = part[(long long)ch * BN_ + i];
            ssum += (double)v.x + (double)v.y;
        }
        unsigned long long u = (unsigned long long)__double_as_longlong(ssum);
        if (u & 0x8000000000000000ULL) u = ~u;
        else                           u |= 0x8000000000000000ULL;
        keys[n] = (u & ~0xFFFULL) | (unsigned long long)(N_ - 1 - n);
    }
    __syncthreads();

    for (int k = 2; k <= N_; k <<= 1) {
        for (int j = k >> 1; j > 2; j >>= 1) {
#pragma unroll
            for (int it = 0; it < 4; it++) {
                int t = tid + it * 1024;
                int ixj = t ^ j;
                if (ixj > t) {
                    unsigned long long a = keys[t];
                    unsigned long long c = keys[ixj];
                    bool desc = ((t & k) == 0);
                    if (desc ? (a < c) : (a > c)) {
                        keys[t] = c;
                        keys[ixj] = a;
                    }
                }
            }
            __syncthreads();
        }
        // register micro-pass: j = min(k/2, 2) down to 1 on elements 4t..4t+3
        {
            int base = tid * 4;
            unsigned long long e0 = keys[base];
            unsigned long long e1 = keys[base + 1];
            unsigned long long e2 = keys[base + 2];
            unsigned long long e3 = keys[base + 3];
            if (k >= 4) {
                bool desc = ((base & k) == 0);
                // j = 2
                if (desc ? (e0 < e2) : (e0 > e2)) { unsigned long long t = e0; e0 = e2; e2 = t; }
                if (desc ? (e1 < e3) : (e1 > e3)) { unsigned long long t = e1; e1 = e3; e3 = t; }
                // j = 1
                if (desc ? (e0 < e1) : (e0 > e1)) { unsigned long long t = e0; e0 = e1; e1 = t; }
                if (desc ? (e2 < e3) : (e2 > e3)) { unsigned long long t = e2; e2 = e3; e3 = t; }
            } else { // k == 2: j = 1, direction alternates per pair
                bool d0 = ((base & 2) == 0);        // true
                bool d1 = (((base + 2) & 2) == 0);  // false
                if (d0 ? (e0 < e1) : (e0 > e1)) { unsigned long long t = e0; e0 = e1; e1 = t; }
                if (d1 ? (e2 < e3) : (e2 > e3)) { unsigned long long t = e2; e2 = e3; e3 = t; }
            }
            keys[base]     = e0;
            keys[base + 1] = e1;
            keys[base + 2] = e2;
            keys[base + 3] = e3;
            __syncthreads();
        }
    }

    idxout[b * K_ + tid] = (N_ - 1) - (int)(keys[tid] & 0xFFFULL);
}

// ---------------------------------------------------------------------------
// Kernel 5: gather selected columns. One thread per output element.
// ---------------------------------------------------------------------------
__global__ __launch_bounds__(256)
void gather_kernel(const float* __restrict__ fx, const float* __restrict__ fy,
                   const int* __restrict__ idx, float* __restrict__ out)
{
    long long t = (long long)blockIdx.x * blockDim.x + threadIdx.x;
    if (t >= 2 * HALF_OUT) return;

    const float* src = fx;
    float* dst = out;
    long long tt = t;
    if (tt >= HALF_OUT) {
        tt -= HALF_OUT;
        src = fy;
        dst = out + HALF_OUT;
    }

    int j = (int)(tt & (K_ - 1));
    long long rest = tt >> 10;          // (b*C + c)*D + d
    int d = (int)(rest % D_);
    long long bc = rest / D_;           // b*C + c
    int b = (int)(bc >> 7);

    int n = idx[b * K_ + j];
    dst[tt] = src[bc * (long long)C_STRIDE + (long long)d * N_ + n];
}

// ---------------------------------------------------------------------------
extern "C" void kernel_launch(void* const* d_in, const int* in_sizes, int n_in,
                              void* d_out, int out_size)
{
    const float* fx = (const float*)d_in[0];
    const float* fy = (const float*)d_in[1];
    float* out = (float*)d_out;

    float2 *mean, *pq, *part;
    int *idx;
    cudaGetSymbolAddress((void**)&mean, g_mean);
    cudaGetSymbolAddress((void**)&pq,   g_pq);
    cudaGetSymbolAddress((void**)&part, g_part);
    cudaGetSymbolAddress((void**)&idx,  g_idx);

    dim3 g1(N_ / 256, B_, 6);
    mean_kernel<<<g1, 256>>>(fx, fy, mean);

    norm_kernel<<<BN_ / 256, 256>>>(mean, pq);

    dim3 g3(N_ / 256, B_, NCHUNK);
    score_kernel<<<g3, 256>>>(fx, fy, pq, part);

    topk_kernel<<<B_, 1024>>>(part, idx);

    long long total = 2 * HALF_OUT;
    int blocks = (int)((total + 255) / 256);
    gather_kernel<<<blocks, 256>>>(fx, fy, idx, out);
}

// round 5
// speedup vs baseline: 2.5538x; 1.0786x over previous
#include <cuda_runtime.h>
#include <stdint.h>

// fx, fy : float32 [B=16, C=128, D=3, N=4096], topk=4 -> k=1024
// Output: concat(fx_sel, fy_sel), each [16,128,3,1024] float32.

#define B_ 16
#define C_ 128
#define D_ 3
#define N_ 4096
#define K_ 1024
#define BN_ (B_ * N_)

#define BATCH_STRIDE  ((long long)C_ * D_ * N_)       // 1,572,864
#define C_STRIDE      (D_ * N_)                       // 12,288
#define HALF_OUT      ((long long)B_ * C_ * D_ * K_)  // 6,291,456

#define NCHUNK 4
#define CPC    (C_ / NCHUNK)   // 32

// Scratch (__device__ globals: allocation-free rule)
__device__ float2 g_mean[6 * BN_];   // (hi, lo) compensated sums, [z][b][n]
__device__ float2 g_pq[6 * BN_];     // p,q as double-single, [z][b][n]
__device__ float2 g_part[NCHUNK * BN_];
__device__ int    g_idx[B_ * K_];

// ---- error-free fp32 transforms (fma pipe; no fp64) ------------------------
__device__ __forceinline__ float2 two_sum(float a, float b) {
    float s  = a + b;
    float bb = s - a;
    float e  = (a - (s - bb)) + (b - bb);
    return make_float2(s, e);
}
__device__ __forceinline__ float2 two_prod(float a, float b) {
    float p = a * b;
    float e = fmaf(a, b, -p);
    return make_float2(p, e);
}

// ---------------------------------------------------------------------------
// Kernel 1: compensated means, float4-vectorized.
// Thread handles 4 consecutive n; z = tensor*3 + d.
// ---------------------------------------------------------------------------
__global__ __launch_bounds__(128)
void mean_kernel(const float* __restrict__ fx, const float* __restrict__ fy,
                 float2* __restrict__ mean)
{
    int n0 = (blockIdx.x * 128 + threadIdx.x) * 4;
    int b = blockIdx.y;
    int z = blockIdx.z;
    const float4* src = (const float4*)((z < 3 ? fx : fy)
                     + (long long)b * BATCH_STRIDE + (long long)(z % 3) * N_ + n0);

    float s[4]  = {0.f, 0.f, 0.f, 0.f};
    float cc[4] = {0.f, 0.f, 0.f, 0.f};
#pragma unroll 4
    for (int c = 0; c < C_; c++) {
        float4 v = src[c * (C_STRIDE / 4)];
        float2 t;
        t = two_sum(s[0], v.x); s[0] = t.x; cc[0] += t.y;
        t = two_sum(s[1], v.y); s[1] = t.x; cc[1] += t.y;
        t = two_sum(s[2], v.z); s[2] = t.x; cc[2] += t.y;
        t = two_sum(s[3], v.w); s[3] = t.x; cc[3] += t.y;
    }
    long long base = (long long)z * BN_ + b * N_ + n0;
#pragma unroll
    for (int i = 0; i < 4; i++)
        mean[base + i] = make_float2(s[i], cc[i]);
}

// ---------------------------------------------------------------------------
// Kernel 2: normalize (tiny fp64: 65k threads).
// ---------------------------------------------------------------------------
__global__ __launch_bounds__(256)
void norm_kernel(const float2* __restrict__ mean, float2* __restrict__ pq)
{
    int i = blockIdx.x * 256 + threadIdx.x;   // b*N + n

    double m[6];
#pragma unroll
    for (int z = 0; z < 6; z++) {
        float2 v = mean[(long long)z * BN_ + i];
        m[z] = ((double)v.x + (double)v.y) * (1.0 / C_);
    }
    double nx = sqrt(m[0]*m[0] + m[1]*m[1] + m[2]*m[2]) + 1e-6;
    double ny = sqrt(m[3]*m[3] + m[4]*m[4] + m[5]*m[5]) + 1e-6;

#pragma unroll
    for (int z = 0; z < 6; z++) {
        double v = m[z] / (z < 3 ? nx : ny);
        float hi = (float)v;
        float lo = (float)(v - (double)hi);
        pq[(long long)z * BN_ + i] = make_float2(hi, lo);
    }
}

// ---------------------------------------------------------------------------
// Kernel 3: partial scores, compensated fp32 (identical math to passing run).
// ---------------------------------------------------------------------------
__global__ __launch_bounds__(256)
void score_kernel(const float* __restrict__ fx, const float* __restrict__ fy,
                  const float2* __restrict__ pq, float2* __restrict__ part)
{
    int n  = blockIdx.x * 256 + threadIdx.x;
    int b  = blockIdx.y;
    int ch = blockIdx.z;
    int i  = b * N_ + n;

    float2 P0 = pq[i];
    float2 P1 = pq[BN_ + i];
    float2 P2 = pq[2 * BN_ + i];
    float2 Q0 = pq[3 * BN_ + i];
    float2 Q1 = pq[4 * BN_ + i];
    float2 Q2 = pq[5 * BN_ + i];

    const float* px = fx + (long long)b * BATCH_STRIDE
                    + (long long)ch * CPC * C_STRIDE + n;
    const float* py = fy + (long long)b * BATCH_STRIDE
                    + (long long)ch * CPC * C_STRIDE + n;

    float sh = 0.f, sl = 0.f;
#pragma unroll 4
    for (int c = 0; c < CPC; c++) {
        const float* rx = px + c * C_STRIDE;
        const float* ry = py + c * C_STRIDE;
        float x0 = rx[0], x1 = rx[N_], x2 = rx[2 * N_];
        float y0 = ry[0], y1 = ry[N_], y2 = ry[2 * N_];

        float2 t = two_prod(x0, P0.x);
        float dxh = t.x;
        float dxl = fmaf(x0, P0.y, t.y);
        t = two_prod(x1, P1.x);
        float2 s = two_sum(dxh, t.x);
        dxh = s.x; dxl += s.y + fmaf(x1, P1.y, t.y);
        t = two_prod(x2, P2.x);
        s = two_sum(dxh, t.x);
        dxh = s.x; dxl += s.y + fmaf(x2, P2.y, t.y);

        t = two_prod(y0, Q0.x);
        float dyh = t.x;
        float dyl = fmaf(y0, Q0.y, t.y);
        t = two_prod(y1, Q1.x);
        s = two_sum(dyh, t.x);
        dyh = s.x; dyl += s.y + fmaf(y1, Q1.y, t.y);
        t = two_prod(y2, Q2.x);
        s = two_sum(dyh, t.x);
        dyh = s.x; dyl += s.y + fmaf(y2, Q2.y, t.y);

        float2 pp = two_prod(dxh, dyh);
        float pe = fmaf(dxh, dyl, fmaf(dxl, dyh, pp.y));
        float2 a = two_sum(sh, pp.x);
        sh = a.x; sl += a.y + pe;
    }
    part[(long long)ch * BN_ + i] = make_float2(sh, sl);
}

// ---------------------------------------------------------------------------
// Kernel 4: combine partials (fp64) -> u64 keys -> exact MSB radix-select of
// the 1024th-largest key -> compact winners -> bitonic sort of 1024 keys
// (j<=16 levels via warp shuffles, no barriers). Keys distinct (index in low
// 12 bits) so pivot is exact; ties resolve by ascending index as lax.top_k.
// ---------------------------------------------------------------------------
__global__ __launch_bounds__(1024)
void topk_kernel(const float2* __restrict__ part, int* __restrict__ idxout)
{
    __shared__ unsigned long long keys[N_];    // 32 KB
    __shared__ unsigned long long skeys[K_];   // 8 KB
    __shared__ unsigned s_hist[256];
    __shared__ unsigned s_sel[2];              // [digit, new rank]
    __shared__ unsigned s_cnt;

    int b = blockIdx.x;
    int tid = threadIdx.x;

    // Build keys (same fp64 combine order as the passing round)
#pragma unroll
    for (int it = 0; it < 4; it++) {
        int n = tid + it * 1024;
        int i = b * N_ + n;
        double ssum = 0.0;
#pragma unroll
        for (int ch = 0; ch < NCHUNK; ch++) {
            float2 v = part[(long long)ch * BN_ + i];
            ssum += (double)v.x + (double)v.y;
        }
        unsigned long long u = (unsigned long long)__double_as_longlong(ssum);
        u = (u & 0x8000000000000000ULL) ? ~u : (u | 0x8000000000000000ULL);
        keys[n] = (u & ~0xFFFULL) | (unsigned long long)(N_ - 1 - n);
    }
    __syncthreads();

    // --- MSB radix select: find pivot = 1024th largest key ---
    unsigned long long prefix = 0;
    unsigned r = K_ - 1;   // 0-based rank (descending) within candidate set
#pragma unroll 1
    for (int p = 0; p < 8; p++) {
        int shift = 56 - 8 * p;
        if (tid < 256) s_hist[tid] = 0;
        __syncthreads();
#pragma unroll
        for (int it = 0; it < 4; it++) {
            unsigned long long key = keys[tid + it * 1024];
            bool match = (p == 0) || (((key ^ prefix) >> (shift + 8)) == 0);
            if (match) atomicAdd(&s_hist[(unsigned)(key >> shift) & 255u], 1u);
        }
        __syncthreads();
        if (tid < 32) {
            unsigned c[8], tot = 0;
#pragma unroll
            for (int i = 0; i < 8; i++) { c[i] = s_hist[tid * 8 + i]; tot += c[i]; }
            unsigned suf = tot;  // inclusive suffix sum over lanes >= tid
#pragma unroll
            for (int o = 1; o < 32; o <<= 1) {
                unsigned v = __shfl_down_sync(0xffffffffu, suf, o);
                if (tid + o < 32) suf += v;
            }
            unsigned above = suf - tot;   // keys with digit in higher lanes
            if (above <= r && r < above + tot) {
                unsigned acc = above;
#pragma unroll
                for (int i = 7; i >= 0; i--) {
                    if (acc + c[i] > r) {
                        s_sel[0] = (unsigned)(tid * 8 + i);
                        s_sel[1] = r - acc;
                        break;
                    }
                    acc += c[i];
                }
            }
        }
        __syncthreads();
        prefix |= ((unsigned long long)s_sel[0]) << shift;
        r = s_sel[1];
        __syncthreads();
    }
    // prefix == pivot key exactly

    // --- Compact the 1024 keys >= pivot ---
    if (tid == 0) s_cnt = 0;
    __syncthreads();
#pragma unroll
    for (int it = 0; it < 4; it++) {
        unsigned long long key = keys[tid + it * 1024];
        if (key >= prefix) {
            unsigned pos = atomicAdd(&s_cnt, 1u);
            skeys[pos] = key;
        }
    }
    __syncthreads();

    // --- Bitonic sort of 1024 keys, descending ---
    for (int k = 2; k <= K_; k <<= 1) {
        for (int j = k >> 1; j >= 32; j >>= 1) {
            int t = tid, ixj = t ^ j;
            if (ixj > t) {
                unsigned long long a = skeys[t];
                unsigned long long c2 = skeys[ixj];
                bool desc = ((t & k) == 0);
                if (desc ? (a < c2) : (a > c2)) { skeys[t] = c2; skeys[ixj] = a; }
            }
            __syncthreads();
        }
        // register phases: j = min(k/2,16) .. 1 via warp shuffles
        {
            unsigned long long v = skeys[tid];
            bool desc = ((tid & k) == 0);
            int jstart = (k >> 1) < 16 ? (k >> 1) : 16;
            for (int j = jstart; j >= 1; j >>= 1) {
                unsigned long long o = __shfl_xor_sync(0xffffffffu, v, j);
                bool lower = ((tid & j) == 0);
                bool takemax = (desc == lower);
                v = takemax ? (v > o ? v : o) : (v < o ? v : o);
            }
            skeys[tid] = v;
            __syncthreads();
        }
    }

    idxout[b * K_ + tid] = (N_ - 1) - (int)(skeys[tid] & 0xFFFULL);
}

// ---------------------------------------------------------------------------
// Kernel 5: gather selected columns. One thread per output element.
// ---------------------------------------------------------------------------
__global__ __launch_bounds__(256)
void gather_kernel(const float* __restrict__ fx, const float* __restrict__ fy,
                   const int* __restrict__ idx, float* __restrict__ out)
{
    long long t = (long long)blockIdx.x * blockDim.x + threadIdx.x;
    if (t >= 2 * HALF_OUT) return;

    const float* src = fx;
    float* dst = out;
    long long tt = t;
    if (tt >= HALF_OUT) {
        tt -= HALF_OUT;
        src = fy;
        dst = out + HALF_OUT;
    }

    int j = (int)(tt & (K_ - 1));
    long long rest = tt >> 10;          // (b*C + c)*D + d
    int d = (int)(rest % D_);
    long long bc = rest / D_;           // b*C + c
    int b = (int)(bc >> 7);

    int n = idx[b * K_ + j];
    dst[tt] = src[bc * (long long)C_STRIDE + (long long)d * N_ + n];
}

// ---------------------------------------------------------------------------
extern "C" void kernel_launch(void* const* d_in, const int* in_sizes, int n_in,
                              void* d_out, int out_size)
{
    const float* fx = (const float*)d_in[0];
    const float* fy = (const float*)d_in[1];
    float* out = (float*)d_out;

    float2 *mean, *pq, *part;
    int *idx;
    cudaGetSymbolAddress((void**)&mean, g_mean);
    cudaGetSymbolAddress((void**)&pq,   g_pq);
    cudaGetSymbolAddress((void**)&part, g_part);
    cudaGetSymbolAddress((void**)&idx,  g_idx);

    dim3 g1(N_ / 512, B_, 6);        // 128 threads, 4 n per thread
    mean_kernel<<<g1, 128>>>(fx, fy, mean);

    norm_kernel<<<BN_ / 256, 256>>>(mean, pq);

    dim3 g3(N_ / 256, B_, NCHUNK);
    score_kernel<<<g3, 256>>>(fx, fy, pq, part);

    topk_kernel<<<B_, 1024>>>(part, idx);

    long long total = 2 * HALF_OUT;
    int blocks = (int)((total + 255) / 256);
    gather_kernel<<<blocks, 256>>>(fx, fy, idx, out);
}

// round 6
// speedup vs baseline: 2.5910x; 1.0146x over previous
#include <cuda_runtime.h>
#include <stdint.h>

// fx, fy : float32 [B=16, C=128, D=3, N=4096], topk=4 -> k=1024
// Output: concat(fx_sel, fy_sel), each [16,128,3,1024] float32.

#define B_ 16
#define C_ 128
#define D_ 3
#define N_ 4096
#define K_ 1024
#define BN_ (B_ * N_)

#define BATCH_STRIDE  ((long long)C_ * D_ * N_)       // 1,572,864
#define C_STRIDE      (D_ * N_)                       // 12,288
#define HALF_OUT      ((long long)B_ * C_ * D_ * K_)  // 6,291,456

#define NCHUNK 4
#define CPC    (C_ / NCHUNK)   // 32

// Scratch (__device__ globals: allocation-free rule)
__device__ float2 g_mean[6 * BN_];   // (hi, lo) compensated sums, [z][b][n]
__device__ float2 g_pq[6 * BN_];     // p,q as double-single, [z][b][n]
__device__ float2 g_part[NCHUNK * BN_];
__device__ int    g_idx[B_ * K_];

// ---- error-free fp32 transforms (fma pipe; no fp64) ------------------------
__device__ __forceinline__ float2 two_sum(float a, float b) {
    float s  = a + b;
    float bb = s - a;
    float e  = (a - (s - bb)) + (b - bb);
    return make_float2(s, e);
}
__device__ __forceinline__ float2 two_prod(float a, float b) {
    float p = a * b;
    float e = fmaf(a, b, -p);
    return make_float2(p, e);
}

// ---------------------------------------------------------------------------
// Kernel 1: compensated means, float4-vectorized. (unchanged from 209us run)
// ---------------------------------------------------------------------------
__global__ __launch_bounds__(128)
void mean_kernel(const float* __restrict__ fx, const float* __restrict__ fy,
                 float2* __restrict__ mean)
{
    int n0 = (blockIdx.x * 128 + threadIdx.x) * 4;
    int b = blockIdx.y;
    int z = blockIdx.z;
    const float4* src = (const float4*)((z < 3 ? fx : fy)
                     + (long long)b * BATCH_STRIDE + (long long)(z % 3) * N_ + n0);

    float s[4]  = {0.f, 0.f, 0.f, 0.f};
    float cc[4] = {0.f, 0.f, 0.f, 0.f};
#pragma unroll 4
    for (int c = 0; c < C_; c++) {
        float4 v = src[c * (C_STRIDE / 4)];
        float2 t;
        t = two_sum(s[0], v.x); s[0] = t.x; cc[0] += t.y;
        t = two_sum(s[1], v.y); s[1] = t.x; cc[1] += t.y;
        t = two_sum(s[2], v.z); s[2] = t.x; cc[2] += t.y;
        t = two_sum(s[3], v.w); s[3] = t.x; cc[3] += t.y;
    }
    long long base = (long long)z * BN_ + b * N_ + n0;
#pragma unroll
    for (int i = 0; i < 4; i++)
        mean[base + i] = make_float2(s[i], cc[i]);
}

// ---------------------------------------------------------------------------
// Kernel 2: normalize (tiny fp64). (unchanged)
// ---------------------------------------------------------------------------
__global__ __launch_bounds__(256)
void norm_kernel(const float2* __restrict__ mean, float2* __restrict__ pq)
{
    int i = blockIdx.x * 256 + threadIdx.x;   // b*N + n

    double m[6];
#pragma unroll
    for (int z = 0; z < 6; z++) {
        float2 v = mean[(long long)z * BN_ + i];
        m[z] = ((double)v.x + (double)v.y) * (1.0 / C_);
    }
    double nx = sqrt(m[0]*m[0] + m[1]*m[1] + m[2]*m[2]) + 1e-6;
    double ny = sqrt(m[3]*m[3] + m[4]*m[4] + m[5]*m[5]) + 1e-6;

#pragma unroll
    for (int z = 0; z < 6; z++) {
        double v = m[z] / (z < 3 ? nx : ny);
        float hi = (float)v;
        float lo = (float)(v - (double)hi);
        pq[(long long)z * BN_ + i] = make_float2(hi, lo);
    }
}

// ---------------------------------------------------------------------------
// Kernel 3: partial scores, compensated fp32. (unchanged math)
// ---------------------------------------------------------------------------
__global__ __launch_bounds__(256)
void score_kernel(const float* __restrict__ fx, const float* __restrict__ fy,
                  const float2* __restrict__ pq, float2* __restrict__ part)
{
    int n  = blockIdx.x * 256 + threadIdx.x;
    int b  = blockIdx.y;
    int ch = blockIdx.z;
    int i  = b * N_ + n;

    float2 P0 = pq[i];
    float2 P1 = pq[BN_ + i];
    float2 P2 = pq[2 * BN_ + i];
    float2 Q0 = pq[3 * BN_ + i];
    float2 Q1 = pq[4 * BN_ + i];
    float2 Q2 = pq[5 * BN_ + i];

    const float* px = fx + (long long)b * BATCH_STRIDE
                    + (long long)ch * CPC * C_STRIDE + n;
    const float* py = fy + (long long)b * BATCH_STRIDE
                    + (long long)ch * CPC * C_STRIDE + n;

    float sh = 0.f, sl = 0.f;
#pragma unroll 4
    for (int c = 0; c < CPC; c++) {
        const float* rx = px + c * C_STRIDE;
        const float* ry = py + c * C_STRIDE;
        float x0 = rx[0], x1 = rx[N_], x2 = rx[2 * N_];
        float y0 = ry[0], y1 = ry[N_], y2 = ry[2 * N_];

        float2 t = two_prod(x0, P0.x);
        float dxh = t.x;
        float dxl = fmaf(x0, P0.y, t.y);
        t = two_prod(x1, P1.x);
        float2 s = two_sum(dxh, t.x);
        dxh = s.x; dxl += s.y + fmaf(x1, P1.y, t.y);
        t = two_prod(x2, P2.x);
        s = two_sum(dxh, t.x);
        dxh = s.x; dxl += s.y + fmaf(x2, P2.y, t.y);

        t = two_prod(y0, Q0.x);
        float dyh = t.x;
        float dyl = fmaf(y0, Q0.y, t.y);
        t = two_prod(y1, Q1.x);
        s = two_sum(dyh, t.x);
        dyh = s.x; dyl += s.y + fmaf(y1, Q1.y, t.y);
        t = two_prod(y2, Q2.x);
        s = two_sum(dyh, t.x);
        dyh = s.x; dyl += s.y + fmaf(y2, Q2.y, t.y);

        float2 pp = two_prod(dxh, dyh);
        float pe = fmaf(dxh, dyl, fmaf(dxl, dyh, pp.y));
        float2 a = two_sum(sh, pp.x);
        sh = a.x; sl += a.y + pe;
    }
    part[(long long)ch * BN_ + i] = make_float2(sh, sl);
}

// ---------------------------------------------------------------------------
// Kernel 4: topk. Early-exit radix select: full 8-bit histogram passes only
// while candidate count m > 128 (typically 2), then compact the <=128
// prefix-matching candidates and brute-force the pivot by rank counting.
// Winners (key >= pivot, exactly 1024 since keys distinct) -> bitonic sort.
// ---------------------------------------------------------------------------
__global__ __launch_bounds__(1024)
void topk_kernel(const float2* __restrict__ part, int* __restrict__ idxout)
{
    __shared__ unsigned long long keys[N_];    // 32 KB
    __shared__ unsigned long long skeys[K_];   // 8 KB
    __shared__ unsigned long long cand[128];   // 1 KB
    __shared__ unsigned long long s_pivot;
    __shared__ unsigned s_hist[256];
    __shared__ unsigned s_sel[3];              // [digit, new rank, count]
    __shared__ unsigned s_cnt;

    int b = blockIdx.x;
    int tid = threadIdx.x;

    // Build keys (same fp64 combine order as the passing rounds)
#pragma unroll
    for (int it = 0; it < 4; it++) {
        int n = tid + it * 1024;
        int i = b * N_ + n;
        double ssum = 0.0;
#pragma unroll
        for (int ch = 0; ch < NCHUNK; ch++) {
            float2 v = part[(long long)ch * BN_ + i];
            ssum += (double)v.x + (double)v.y;
        }
        unsigned long long u = (unsigned long long)__double_as_longlong(ssum);
        u = (u & 0x8000000000000000ULL) ? ~u : (u | 0x8000000000000000ULL);
        keys[n] = (u & ~0xFFFULL) | (unsigned long long)(N_ - 1 - n);
    }
    if (tid == 0) s_cnt = 0;
    __syncthreads();

    // --- radix passes while candidate set is large ---
    unsigned long long prefix = 0;
    unsigned r = K_ - 1;        // 0-based rank (descending) within candidates
    unsigned m = N_;
    int done_shift = 64;
#pragma unroll 1
    for (int p = 0; p < 8 && m > 128; p++) {
        int shift = 56 - 8 * p;
        if (tid < 256) s_hist[tid] = 0;
        __syncthreads();
#pragma unroll
        for (int it = 0; it < 4; it++) {
            unsigned long long key = keys[tid + it * 1024];
            bool match = (p == 0) || (((key ^ prefix) >> (shift + 8)) == 0);
            if (match) atomicAdd(&s_hist[(unsigned)(key >> shift) & 255u], 1u);
        }
        __syncthreads();
        if (tid < 32) {
            unsigned c[8], tot = 0;
#pragma unroll
            for (int i = 0; i < 8; i++) { c[i] = s_hist[tid * 8 + i]; tot += c[i]; }
            unsigned suf = tot;  // inclusive suffix sum over lanes >= tid
#pragma unroll
            for (int o = 1; o < 32; o <<= 1) {
                unsigned v = __shfl_down_sync(0xffffffffu, suf, o);
                if (tid + o < 32) suf += v;
            }
            unsigned above = suf - tot;
            if (above <= r && r < above + tot) {
                unsigned acc = above;
#pragma unroll
                for (int i = 7; i >= 0; i--) {
                    if (acc + c[i] > r) {
                        s_sel[0] = (unsigned)(tid * 8 + i);
                        s_sel[1] = r - acc;
                        s_sel[2] = c[i];
                        break;
                    }
                    acc += c[i];
                }
            }
        }
        __syncthreads();
        prefix |= ((unsigned long long)s_sel[0]) << shift;
        r = s_sel[1];
        m = s_sel[2];
        done_shift = shift;
        __syncthreads();
    }

    // --- compact the m (<=128) prefix-matching candidates ---
#pragma unroll
    for (int it = 0; it < 4; it++) {
        unsigned long long key = keys[tid + it * 1024];
        if ((key >> done_shift) == (prefix >> done_shift)) {
            unsigned pos = atomicAdd(&s_cnt, 1u);
            cand[pos] = key;
        }
    }
    __syncthreads();

    // --- brute-force pivot: candidate with exactly r larger candidates ---
    if (tid < m) {
        unsigned long long mykey = cand[tid];
        unsigned cnt = 0;
        for (unsigned j = 0; j < m; j++)
            cnt += (cand[j] > mykey) ? 1u : 0u;
        if (cnt == r) s_pivot = mykey;
    }
    if (tid == 0) s_cnt = 0;
    __syncthreads();
    unsigned long long pivot = s_pivot;

    // --- compact the exactly-1024 winners (keys >= pivot) ---
#pragma unroll
    for (int it = 0; it < 4; it++) {
        unsigned long long key = keys[tid + it * 1024];
        if (key >= pivot) {
            unsigned pos = atomicAdd(&s_cnt, 1u);
            skeys[pos] = key;
        }
    }
    __syncthreads();

    // --- bitonic sort of 1024 keys, descending (j<=16 via warp shuffles) ---
    for (int k = 2; k <= K_; k <<= 1) {
        for (int j = k >> 1; j >= 32; j >>= 1) {
            int t = tid, ixj = t ^ j;
            if (ixj > t) {
                unsigned long long a = skeys[t];
                unsigned long long c2 = skeys[ixj];
                bool desc = ((t & k) == 0);
                if (desc ? (a < c2) : (a > c2)) { skeys[t] = c2; skeys[ixj] = a; }
            }
            __syncthreads();
        }
        {
            unsigned long long v = skeys[tid];
            bool desc = ((tid & k) == 0);
            int jstart = (k >> 1) < 16 ? (k >> 1) : 16;
            for (int j = jstart; j >= 1; j >>= 1) {
                unsigned long long o = __shfl_xor_sync(0xffffffffu, v, j);
                bool lower = ((tid & j) == 0);
                bool takemax = (desc == lower);
                v = takemax ? (v > o ? v : o) : (v < o ? v : o);
            }
            skeys[tid] = v;
            __syncthreads();
        }
    }

    idxout[b * K_ + tid] = (N_ - 1) - (int)(skeys[tid] & 0xFFFULL);
}

// ---------------------------------------------------------------------------
// Kernel 5: gather selected columns. (unchanged)
// ---------------------------------------------------------------------------
__global__ __launch_bounds__(256)
void gather_kernel(const float* __restrict__ fx, const float* __restrict__ fy,
                   const int* __restrict__ idx, float* __restrict__ out)
{
    long long t = (long long)blockIdx.x * blockDim.x + threadIdx.x;
    if (t >= 2 * HALF_OUT) return;

    const float* src = fx;
    float* dst = out;
    long long tt = t;
    if (tt >= HALF_OUT) {
        tt -= HALF_OUT;
        src = fy;
        dst = out + HALF_OUT;
    }

    int j = (int)(tt & (K_ - 1));
    long long rest = tt >> 10;          // (b*C + c)*D + d
    int d = (int)(rest % D_);
    long long bc = rest / D_;           // b*C + c
    int b = (int)(bc >> 7);

    int n = idx[b * K_ + j];
    dst[tt] = src[bc * (long long)C_STRIDE + (long long)d * N_ + n];
}

// ---------------------------------------------------------------------------
extern "C" void kernel_launch(void* const* d_in, const int* in_sizes, int n_in,
                              void* d_out, int out_size)
{
    const float* fx = (const float*)d_in[0];
    const float* fy = (const float*)d_in[1];
    float* out = (float*)d_out;

    float2 *mean, *pq, *part;
    int *idx;
    cudaGetSymbolAddress((void**)&mean, g_mean);
    cudaGetSymbolAddress((void**)&pq,   g_pq);
    cudaGetSymbolAddress((void**)&part, g_part);
    cudaGetSymbolAddress((void**)&idx,  g_idx);

    dim3 g1(N_ / 512, B_, 6);        // 128 threads, 4 n per thread
    mean_kernel<<<g1, 128>>>(fx, fy, mean);

    norm_kernel<<<BN_ / 256, 256>>>(mean, pq);

    dim3 g3(N_ / 256, B_, NCHUNK);
    score_kernel<<<g3, 256>>>(fx, fy, pq, part);

    topk_kernel<<<B_, 1024>>>(part, idx);

    long long total = 2 * HALF_OUT;
    int blocks = (int)((total + 255) / 256);
    gather_kernel<<<blocks, 256>>>(fx, fy, idx, out);
}

// round 7
// speedup vs baseline: 3.4640x; 1.3369x over previous
#include <cuda_runtime.h>
#include <stdint.h>

// fx, fy : float32 [B=16, C=128, D=3, N=4096], topk=4 -> k=1024
// Output: concat(fx_sel, fy_sel), each [16,128,3,1024] float32.

#define B_ 16
#define C_ 128
#define D_ 3
#define N_ 4096
#define K_ 1024
#define BN_ (B_ * N_)

#define BATCH_STRIDE  ((long long)C_ * D_ * N_)       // 1,572,864
#define C_STRIDE      (D_ * N_)                       // 12,288
#define HALF_OUT      ((long long)B_ * C_ * D_ * K_)  // 6,291,456

#define NCHUNK 4
#define CPC    (C_ / NCHUNK)   // 32
#define NQ     15              // 6 means + 9 cross-moments

// Scratch (__device__ globals: allocation-free rule)
__device__ float2             g_stats[NCHUNK * NQ * BN_];  // (sum, kahan-c)
__device__ unsigned long long g_key[BN_];
__device__ int                g_idx[B_ * K_];

__device__ __forceinline__ void kadd(float& s, float& c, float v)
{
    float y = v - c;
    float t = s + y;
    c = (t - s) - y;
    s = t;
}

// ---------------------------------------------------------------------------
// Kernel 1 (fused streaming): per (b,n,chunk) accumulate, over 32 c's,
//   q0..q5  : Kahan sums of x0,x1,x2,y0,y1,y2        (means)
//   q6..q14 : Kahan sums of x_i * y_j                (M cross-moments)
// Single pass over the 201 MB input. 69 fp32 ops / c / thread.
// ---------------------------------------------------------------------------
__global__ __launch_bounds__(256)
void stats_kernel(const float* __restrict__ fx, const float* __restrict__ fy,
                  float2* __restrict__ stats)
{
    int n  = blockIdx.x * 256 + threadIdx.x;
    int b  = blockIdx.y;
    int ch = blockIdx.z;
    int i  = b * N_ + n;

    const float* px = fx + (long long)b * BATCH_STRIDE
                    + (long long)ch * CPC * C_STRIDE + n;
    const float* py = fy + (long long)b * BATCH_STRIDE
                    + (long long)ch * CPC * C_STRIDE + n;

    float s[NQ], c[NQ];
#pragma unroll
    for (int q = 0; q < NQ; q++) { s[q] = 0.f; c[q] = 0.f; }

#pragma unroll 4
    for (int cc = 0; cc < CPC; cc++) {
        const float* rx = px + cc * C_STRIDE;
        const float* ry = py + cc * C_STRIDE;
        float x0 = rx[0], x1 = rx[N_], x2 = rx[2 * N_];
        float y0 = ry[0], y1 = ry[N_], y2 = ry[2 * N_];

        kadd(s[0], c[0], x0);
        kadd(s[1], c[1], x1);
        kadd(s[2], c[2], x2);
        kadd(s[3], c[3], y0);
        kadd(s[4], c[4], y1);
        kadd(s[5], c[5], y2);

        kadd(s[6],  c[6],  x0 * y0);
        kadd(s[7],  c[7],  x0 * y1);
        kadd(s[8],  c[8],  x0 * y2);
        kadd(s[9],  c[9],  x1 * y0);
        kadd(s[10], c[10], x1 * y1);
        kadd(s[11], c[11], x1 * y2);
        kadd(s[12], c[12], x2 * y0);
        kadd(s[13], c[13], x2 * y1);
        kadd(s[14], c[14], x2 * y2);
    }

#pragma unroll
    for (int q = 0; q < NQ; q++)
        stats[((long long)ch * NQ + q) * BN_ + i] = make_float2(s[q], c[q]);
}

// ---------------------------------------------------------------------------
// Kernel 2 (combine): fp64 sum of chunk partials (fixed order), normalize
// means, contract s = p^T M q, emit sortable u64 key with (4095-n) packed in
// the low 12 bits (smaller index wins ties, matching jax.lax.top_k).
// 65k threads x ~150 fp64 ops — negligible.
// ---------------------------------------------------------------------------
__global__ __launch_bounds__(256)
void key_kernel(const float2* __restrict__ stats,
                unsigned long long* __restrict__ key)
{
    int i = blockIdx.x * 256 + threadIdx.x;   // b*N + n
    int n = i & (N_ - 1);

    double S[NQ];
#pragma unroll
    for (int q = 0; q < NQ; q++) {
        double acc = 0.0;
#pragma unroll
        for (int ch = 0; ch < NCHUNK; ch++) {
            float2 v = stats[((long long)ch * NQ + q) * BN_ + i];
            acc += (double)v.x + (double)v.y;
        }
        S[q] = acc;
    }

    double mx0 = S[0] * (1.0 / C_), mx1 = S[1] * (1.0 / C_), mx2 = S[2] * (1.0 / C_);
    double my0 = S[3] * (1.0 / C_), my1 = S[4] * (1.0 / C_), my2 = S[5] * (1.0 / C_);

    double nx = sqrt(mx0 * mx0 + mx1 * mx1 + mx2 * mx2) + 1e-6;
    double ny = sqrt(my0 * my0 + my1 * my1 + my2 * my2) + 1e-6;

    double p0 = mx0 / nx, p1 = mx1 / nx, p2 = mx2 / nx;
    double q0 = my0 / ny, q1 = my1 / ny, q2 = my2 / ny;

    double v0 = S[6]  * q0 + S[7]  * q1 + S[8]  * q2;
    double v1 = S[9]  * q0 + S[10] * q1 + S[11] * q2;
    double v2 = S[12] * q0 + S[13] * q1 + S[14] * q2;

    double sc = p0 * v0 + p1 * v1 + p2 * v2;

    unsigned long long u = (unsigned long long)__double_as_longlong(sc);
    u = (u & 0x8000000000000000ULL) ? ~u : (u | 0x8000000000000000ULL);
    key[i] = (u & ~0xFFFULL) | (unsigned long long)(N_ - 1 - n);
}

// ---------------------------------------------------------------------------
// Kernel 3: topk. Early-exit radix select on prebuilt keys, brute-force pivot
// among <=128 candidates, compact 1024 winners, bitonic sort (warp phases in
// registers). Keys distinct -> pivot exact, exactly 1024 winners.
// ---------------------------------------------------------------------------
__global__ __launch_bounds__(1024)
void topk_kernel(const unsigned long long* __restrict__ keyg,
                 int* __restrict__ idxout)
{
    __shared__ unsigned long long keys[N_];    // 32 KB
    __shared__ unsigned long long skeys[K_];   // 8 KB
    __shared__ unsigned long long cand[128];
    __shared__ unsigned long long s_pivot;
    __shared__ unsigned s_hist[256];
    __shared__ unsigned s_sel[3];              // [digit, new rank, count]
    __shared__ unsigned s_cnt;

    int b = blockIdx.x;
    int tid = threadIdx.x;

#pragma unroll
    for (int it = 0; it < 4; it++) {
        int n = tid + it * 1024;
        keys[n] = keyg[b * N_ + n];
    }
    if (tid == 0) s_cnt = 0;
    __syncthreads();

    unsigned long long prefix = 0;
    unsigned r = K_ - 1;
    unsigned m = N_;
    int done_shift = 64;
#pragma unroll 1
    for (int p = 0; p < 8 && m > 128; p++) {
        int shift = 56 - 8 * p;
        if (tid < 256) s_hist[tid] = 0;
        __syncthreads();
#pragma unroll
        for (int it = 0; it < 4; it++) {
            unsigned long long key = keys[tid + it * 1024];
            bool match = (p == 0) || (((key ^ prefix) >> (shift + 8)) == 0);
            if (match) atomicAdd(&s_hist[(unsigned)(key >> shift) & 255u], 1u);
        }
        __syncthreads();
        if (tid < 32) {
            unsigned c[8], tot = 0;
#pragma unroll
            for (int i = 0; i < 8; i++) { c[i] = s_hist[tid * 8 + i]; tot += c[i]; }
            unsigned suf = tot;
#pragma unroll
            for (int o = 1; o < 32; o <<= 1) {
                unsigned v = __shfl_down_sync(0xffffffffu, suf, o);
                if (tid + o < 32) suf += v;
            }
            unsigned above = suf - tot;
            if (above <= r && r < above + tot) {
                unsigned acc = above;
#pragma unroll
                for (int i = 7; i >= 0; i--) {
                    if (acc + c[i] > r) {
                        s_sel[0] = (unsigned)(tid * 8 + i);
                        s_sel[1] = r - acc;
                        s_sel[2] = c[i];
                        break;
                    }
                    acc += c[i];
                }
            }
        }
        __syncthreads();
        prefix |= ((unsigned long long)s_sel[0]) << shift;
        r = s_sel[1];
        m = s_sel[2];
        done_shift = shift;
        __syncthreads();
    }

#pragma unroll
    for (int it = 0; it < 4; it++) {
        unsigned long long key = keys[tid + it * 1024];
        if ((key >> done_shift) == (prefix >> done_shift)) {
            unsigned pos = atomicAdd(&s_cnt, 1u);
            cand[pos] = key;
        }
    }
    __syncthreads();

    if (tid < m) {
        unsigned long long mykey = cand[tid];
        unsigned cnt = 0;
        for (unsigned j = 0; j < m; j++)
            cnt += (cand[j] > mykey) ? 1u : 0u;
        if (cnt == r) s_pivot = mykey;
    }
    if (tid == 0) s_cnt = 0;
    __syncthreads();
    unsigned long long pivot = s_pivot;

#pragma unroll
    for (int it = 0; it < 4; it++) {
        unsigned long long key = keys[tid + it * 1024];
        if (key >= pivot) {
            unsigned pos = atomicAdd(&s_cnt, 1u);
            skeys[pos] = key;
        }
    }
    __syncthreads();

    for (int k = 2; k <= K_; k <<= 1) {
        for (int j = k >> 1; j >= 32; j >>= 1) {
            int t = tid, ixj = t ^ j;
            if (ixj > t) {
                unsigned long long a = skeys[t];
                unsigned long long c2 = skeys[ixj];
                bool desc = ((t & k) == 0);
                if (desc ? (a < c2) : (a > c2)) { skeys[t] = c2; skeys[ixj] = a; }
            }
            __syncthreads();
        }
        {
            unsigned long long v = skeys[tid];
            bool desc = ((tid & k) == 0);
            int jstart = (k >> 1) < 16 ? (k >> 1) : 16;
            for (int j = jstart; j >= 1; j >>= 1) {
                unsigned long long o = __shfl_xor_sync(0xffffffffu, v, j);
                bool lower = ((tid & j) == 0);
                bool takemax = (desc == lower);
                v = takemax ? (v > o ? v : o) : (v < o ? v : o);
            }
            skeys[tid] = v;
            __syncthreads();
        }
    }

    idxout[b * K_ + tid] = (N_ - 1) - (int)(skeys[tid] & 0xFFFULL);
}

// ---------------------------------------------------------------------------
// Kernel 4: gather, float4 output vectorization (4 j per thread).
// idx loads int4-coalesced; scattered 4B reads get 4x MLP per thread.
// ---------------------------------------------------------------------------
__global__ __launch_bounds__(256)
void gather_kernel(const float* __restrict__ fx, const float* __restrict__ fy,
                   const int* __restrict__ idx, float* __restrict__ out)
{
    long long t = (long long)blockIdx.x * blockDim.x + threadIdx.x;
    long long e = t * 4;                 // element index (multiple of 4)
    if (e >= 2 * HALF_OUT) return;

    const float* src = fx;
    float* dst = out;
    long long tt = e;
    if (tt >= HALF_OUT) {
        tt -= HALF_OUT;
        src = fy;
        dst = out + HALF_OUT;
    }

    int j0 = (int)(tt & (K_ - 1));       // multiple of 4
    long long rest = tt >> 10;           // (b*C + c)*D + d
    int d = (int)(rest % D_);
    long long bc = rest / D_;            // b*C + c
    int b = (int)(bc >> 7);

    int4 nn = *(const int4*)&idx[b * K_ + j0];
    const float* row = src + bc * (long long)C_STRIDE + (long long)d * N_;

    float4 v;
    v.x = row[nn.x];
    v.y = row[nn.y];
    v.z = row[nn.z];
    v.w = row[nn.w];
    *(float4*)&dst[tt] = v;
}

// ---------------------------------------------------------------------------
extern "C" void kernel_launch(void* const* d_in, const int* in_sizes, int n_in,
                              void* d_out, int out_size)
{
    const float* fx = (const float*)d_in[0];
    const float* fy = (const float*)d_in[1];
    float* out = (float*)d_out;

    float2* stats;
    unsigned long long* key;
    int* idx;
    cudaGetSymbolAddress((void**)&stats, g_stats);
    cudaGetSymbolAddress((void**)&key,   g_key);
    cudaGetSymbolAddress((void**)&idx,   g_idx);

    dim3 g1(N_ / 256, B_, NCHUNK);
    stats_kernel<<<g1, 256>>>(fx, fy, stats);

    key_kernel<<<BN_ / 256, 256>>>(stats, key);

    topk_kernel<<<B_, 1024>>>(key, idx);

    long long total_vec = (2 * HALF_OUT) / 4;
    int blocks = (int)((total_vec + 255) / 256);
    gather_kernel<<<blocks, 256>>>(fx, fy, idx, out);
}

// round 8
// speedup vs baseline: 3.7243x; 1.0751x over previous
#include <cuda_runtime.h>
#include <stdint.h>

// fx, fy : float32 [B=16, C=128, D=3, N=4096], topk=4 -> k=1024
// Output: concat(fx_sel, fy_sel), each [16,128,3,1024] float32.

#define B_ 16
#define C_ 128
#define D_ 3
#define N_ 4096
#define K_ 1024
#define BN_ (B_ * N_)

#define BATCH_STRIDE  ((long long)C_ * D_ * N_)       // 1,572,864
#define C_STRIDE      (D_ * N_)                       // 12,288
#define HALF_OUT      ((long long)B_ * C_ * D_ * K_)  // 6,291,456

#define NCHUNK 4
#define CPC    (C_ / NCHUNK)   // 32
#define NQ     15              // 6 means + 9 cross-moments

// Scratch (__device__ globals: allocation-free rule)
__device__ float2             g_stats[NCHUNK * NQ * BN_];  // (sum, kahan-c)
__device__ unsigned long long g_key[BN_];
__device__ unsigned           g_hist1[B_ * 256];           // pass-0 histograms
__device__ int                g_idx[B_ * K_];

__device__ __forceinline__ void kadd(float& s, float& c, float v)
{
    float y = v - c;
    float t = s + y;
    c = (t - s) - y;
    s = t;
}

// ---------------------------------------------------------------------------
// Kernel 1 (fused streaming): per (b, n-pair, chunk) accumulate over 32 c's,
//   q0..q5  : Kahan sums of x0,x1,x2,y0,y1,y2        (means)
//   q6..q14 : Kahan sums of x_i * y_j                (M cross-moments)
// Each thread owns 2 consecutive n (float2 loads; per-n math order unchanged).
// Block (0,0,0) also zeroes g_hist1 for this replay (key_kernel runs after).
// ---------------------------------------------------------------------------
__global__ __launch_bounds__(256)
void stats_kernel(const float* __restrict__ fx, const float* __restrict__ fy,
                  float2* __restrict__ stats, unsigned* __restrict__ hist1)
{
    if (blockIdx.x == 0 && blockIdx.y == 0 && blockIdx.z == 0) {
        for (int j = threadIdx.x; j < B_ * 256; j += 256) hist1[j] = 0;
    }

    int n0 = (blockIdx.x * 256 + threadIdx.x) * 2;
    int b  = blockIdx.y;
    int ch = blockIdx.z;
    int i  = b * N_ + n0;

    const float2* px = (const float2*)(fx + (long long)b * BATCH_STRIDE
                     + (long long)ch * CPC * C_STRIDE + n0);
    const float2* py = (const float2*)(fy + (long long)b * BATCH_STRIDE
                     + (long long)ch * CPC * C_STRIDE + n0);

    float s[NQ][2], c[NQ][2];
#pragma unroll
    for (int q = 0; q < NQ; q++) {
        s[q][0] = 0.f; s[q][1] = 0.f;
        c[q][0] = 0.f; c[q][1] = 0.f;
    }

#pragma unroll 4
    for (int cc = 0; cc < CPC; cc++) {
        float2 X0 = px[cc * (C_STRIDE / 2)];
        float2 X1 = px[cc * (C_STRIDE / 2) + N_ / 2];
        float2 X2 = px[cc * (C_STRIDE / 2) + N_];
        float2 Y0 = py[cc * (C_STRIDE / 2)];
        float2 Y1 = py[cc * (C_STRIDE / 2) + N_ / 2];
        float2 Y2 = py[cc * (C_STRIDE / 2) + N_];

        float xs[2][3] = {{X0.x, X1.x, X2.x}, {X0.y, X1.y, X2.y}};
        float ys[2][3] = {{Y0.x, Y1.x, Y2.x}, {Y0.y, Y1.y, Y2.y}};

#pragma unroll
        for (int l = 0; l < 2; l++) {
            kadd(s[0][l], c[0][l], xs[l][0]);
            kadd(s[1][l], c[1][l], xs[l][1]);
            kadd(s[2][l], c[2][l], xs[l][2]);
            kadd(s[3][l], c[3][l], ys[l][0]);
            kadd(s[4][l], c[4][l], ys[l][1]);
            kadd(s[5][l], c[5][l], ys[l][2]);

            kadd(s[6][l],  c[6][l],  xs[l][0] * ys[l][0]);
            kadd(s[7][l],  c[7][l],  xs[l][0] * ys[l][1]);
            kadd(s[8][l],  c[8][l],  xs[l][0] * ys[l][2]);
            kadd(s[9][l],  c[9][l],  xs[l][1] * ys[l][0]);
            kadd(s[10][l], c[10][l], xs[l][1] * ys[l][1]);
            kadd(s[11][l], c[11][l], xs[l][1] * ys[l][2]);
            kadd(s[12][l], c[12][l], xs[l][2] * ys[l][0]);
            kadd(s[13][l], c[13][l], xs[l][2] * ys[l][1]);
            kadd(s[14][l], c[14][l], xs[l][2] * ys[l][2]);
        }
    }

#pragma unroll
    for (int q = 0; q < NQ; q++) {
        stats[((long long)ch * NQ + q) * BN_ + i]     = make_float2(s[q][0], c[q][0]);
        stats[((long long)ch * NQ + q) * BN_ + i + 1] = make_float2(s[q][1], c[q][1]);
    }
}

// ---------------------------------------------------------------------------
// Kernel 2 (combine): fp64 sum of chunk partials (fixed order), normalize
// means, contract s = p^T M q, emit sortable u64 key with (4095-n) in the low
// 12 bits. ALSO builds the per-batch 256-bin top-digit histogram chip-wide,
// so topk can skip its most expensive radix pass.
// ---------------------------------------------------------------------------
__global__ __launch_bounds__(256)
void key_kernel(const float2* __restrict__ stats,
                unsigned long long* __restrict__ key,
                unsigned* __restrict__ hist1)
{
    int i = blockIdx.x * 256 + threadIdx.x;   // b*N + n
    int n = i & (N_ - 1);
    int b = i >> 12;

    double S[NQ];
#pragma unroll
    for (int q = 0; q < NQ; q++) {
        double acc = 0.0;
#pragma unroll
        for (int ch = 0; ch < NCHUNK; ch++) {
            float2 v = stats[((long long)ch * NQ + q) * BN_ + i];
            acc += (double)v.x + (double)v.y;
        }
        S[q] = acc;
    }

    double mx0 = S[0] * (1.0 / C_), mx1 = S[1] * (1.0 / C_), mx2 = S[2] * (1.0 / C_);
    double my0 = S[3] * (1.0 / C_), my1 = S[4] * (1.0 / C_), my2 = S[5] * (1.0 / C_);

    double nx = sqrt(mx0 * mx0 + mx1 * mx1 + mx2 * mx2) + 1e-6;
    double ny = sqrt(my0 * my0 + my1 * my1 + my2 * my2) + 1e-6;

    double p0 = mx0 / nx, p1 = mx1 / nx, p2 = mx2 / nx;
    double q0 = my0 / ny, q1 = my1 / ny, q2 = my2 / ny;

    double v0 = S[6]  * q0 + S[7]  * q1 + S[8]  * q2;
    double v1 = S[9]  * q0 + S[10] * q1 + S[11] * q2;
    double v2 = S[12] * q0 + S[13] * q1 + S[14] * q2;

    double sc = p0 * v0 + p1 * v1 + p2 * v2;

    unsigned long long u = (unsigned long long)__double_as_longlong(sc);
    u = (u & 0x8000000000000000ULL) ? ~u : (u | 0x8000000000000000ULL);
    unsigned long long k = (u & ~0xFFFULL) | (unsigned long long)(N_ - 1 - n);
    key[i] = k;

    atomicAdd(&hist1[b * 256 + (unsigned)(k >> 56)], 1u);
}

// ---------------------------------------------------------------------------
// Kernel 3: topk. Pass-0 histogram is prebuilt (g_hist1); remaining radix
// passes (cheap: few matching keys) run until <=128 candidates, brute-force
// pivot, compact 1024 winners, bitonic sort (warp phases in registers).
// ---------------------------------------------------------------------------
__global__ __launch_bounds__(1024)
void topk_kernel(const unsigned long long* __restrict__ keyg,
                 const unsigned* __restrict__ hist1,
                 int* __restrict__ idxout)
{
    __shared__ unsigned long long keys[N_];    // 32 KB
    __shared__ unsigned long long skeys[K_];   // 8 KB
    __shared__ unsigned long long cand[128];
    __shared__ unsigned long long s_pivot;
    __shared__ unsigned s_hist[256];
    __shared__ unsigned s_sel[3];              // [digit, new rank, count]
    __shared__ unsigned s_cnt;

    int b = blockIdx.x;
    int tid = threadIdx.x;

#pragma unroll
    for (int it = 0; it < 4; it++) {
        int n = tid + it * 1024;
        keys[n] = keyg[b * N_ + n];
    }
    if (tid == 0) s_cnt = 0;
    __syncthreads();

    unsigned long long prefix = 0;
    unsigned r = K_ - 1;
    unsigned m = N_;
    int done_shift = 64;
#pragma unroll 1
    for (int p = 0; p < 8 && m > 128; p++) {
        int shift = 56 - 8 * p;
        if (p == 0) {
            if (tid < 256) s_hist[tid] = hist1[b * 256 + tid];
        } else {
            if (tid < 256) s_hist[tid] = 0;
            __syncthreads();
#pragma unroll
            for (int it = 0; it < 4; it++) {
                unsigned long long key = keys[tid + it * 1024];
                if (((key ^ prefix) >> (shift + 8)) == 0)
                    atomicAdd(&s_hist[(unsigned)(key >> shift) & 255u], 1u);
            }
        }
        __syncthreads();
        if (tid < 32) {
            unsigned c[8], tot = 0;
#pragma unroll
            for (int i = 0; i < 8; i++) { c[i] = s_hist[tid * 8 + i]; tot += c[i]; }
            unsigned suf = tot;
#pragma unroll
            for (int o = 1; o < 32; o <<= 1) {
                unsigned v = __shfl_down_sync(0xffffffffu, suf, o);
                if (tid + o < 32) suf += v;
            }
            unsigned above = suf - tot;
            if (above <= r && r < above + tot) {
                unsigned acc = above;
#pragma unroll
                for (int i = 7; i >= 0; i--) {
                    if (acc + c[i] > r) {
                        s_sel[0] = (unsigned)(tid * 8 + i);
                        s_sel[1] = r - acc;
                        s_sel[2] = c[i];
                        break;
                    }
                    acc += c[i];
                }
            }
        }
        __syncthreads();
        prefix |= ((unsigned long long)s_sel[0]) << shift;
        r = s_sel[1];
        m = s_sel[2];
        done_shift = shift;
        __syncthreads();
    }

#pragma unroll
    for (int it = 0; it < 4; it++) {
        unsigned long long key = keys[tid + it * 1024];
        if ((key >> done_shift) == (prefix >> done_shift)) {
            unsigned pos = atomicAdd(&s_cnt, 1u);
            cand[pos] = key;
        }
    }
    __syncthreads();

    if (tid < m) {
        unsigned long long mykey = cand[tid];
        unsigned cnt = 0;
        for (unsigned j = 0; j < m; j++)
            cnt += (cand[j] > mykey) ? 1u : 0u;
        if (cnt == r) s_pivot = mykey;
    }
    if (tid == 0) s_cnt = 0;
    __syncthreads();
    unsigned long long pivot = s_pivot;

#pragma unroll
    for (int it = 0; it < 4; it++) {
        unsigned long long key = keys[tid + it * 1024];
        if (key >= pivot) {
            unsigned pos = atomicAdd(&s_cnt, 1u);
            skeys[pos] = key;
        }
    }
    __syncthreads();

    for (int k = 2; k <= K_; k <<= 1) {
        for (int j = k >> 1; j >= 32; j >>= 1) {
            int t = tid, ixj = t ^ j;
            if (ixj > t) {
                unsigned long long a = skeys[t];
                unsigned long long c2 = skeys[ixj];
                bool desc = ((t & k) == 0);
                if (desc ? (a < c2) : (a > c2)) { skeys[t] = c2; skeys[ixj] = a; }
            }
            __syncthreads();
        }
        {
            unsigned long long v = skeys[tid];
            bool desc = ((tid & k) == 0);
            int jstart = (k >> 1) < 16 ? (k >> 1) : 16;
            for (int j = jstart; j >= 1; j >>= 1) {
                unsigned long long o = __shfl_xor_sync(0xffffffffu, v, j);
                bool lower = ((tid & j) == 0);
                bool takemax = (desc == lower);
                v = takemax ? (v > o ? v : o) : (v < o ? v : o);
            }
            skeys[tid] = v;
            __syncthreads();
        }
    }

    idxout[b * K_ + tid] = (N_ - 1) - (int)(skeys[tid] & 0xFFFULL);
}

// ---------------------------------------------------------------------------
// Kernel 4: gather, float4 output vectorization (4 j per thread).
// ---------------------------------------------------------------------------
__global__ __launch_bounds__(256)
void gather_kernel(const float* __restrict__ fx, const float* __restrict__ fy,
                   const int* __restrict__ idx, float* __restrict__ out)
{
    long long t = (long long)blockIdx.x * blockDim.x + threadIdx.x;
    long long e = t * 4;                 // element index (multiple of 4)
    if (e >= 2 * HALF_OUT) return;

    const float* src = fx;
    float* dst = out;
    long long tt = e;
    if (tt >= HALF_OUT) {
        tt -= HALF_OUT;
        src = fy;
        dst = out + HALF_OUT;
    }

    int j0 = (int)(tt & (K_ - 1));       // multiple of 4
    long long rest = tt >> 10;           // (b*C + c)*D + d
    int d = (int)(rest % D_);
    long long bc = rest / D_;            // b*C + c
    int b = (int)(bc >> 7);

    int4 nn = *(const int4*)&idx[b * K_ + j0];
    const float* row = src + bc * (long long)C_STRIDE + (long long)d * N_;

    float4 v;
    v.x = row[nn.x];
    v.y = row[nn.y];
    v.z = row[nn.z];
    v.w = row[nn.w];
    *(float4*)&dst[tt] = v;
}

// ---------------------------------------------------------------------------
extern "C" void kernel_launch(void* const* d_in, const int* in_sizes, int n_in,
                              void* d_out, int out_size)
{
    const float* fx = (const float*)d_in[0];
    const float* fy = (const float*)d_in[1];
    float* out = (float*)d_out;

    float2* stats;
    unsigned long long* key;
    unsigned* hist1;
    int* idx;
    cudaGetSymbolAddress((void**)&stats, g_stats);
    cudaGetSymbolAddress((void**)&key,   g_key);
    cudaGetSymbolAddress((void**)&hist1, g_hist1);
    cudaGetSymbolAddress((void**)&idx,   g_idx);

    dim3 g1(N_ / 512, B_, NCHUNK);       // 2 n per thread
    stats_kernel<<<g1, 256>>>(fx, fy, stats, hist1);

    key_kernel<<<BN_ / 256, 256>>>(stats, key, hist1);

    topk_kernel<<<B_, 1024>>>(key, hist1, idx);

    long long total_vec = (2 * HALF_OUT) / 4;
    int blocks = (int)((total_vec + 255) / 256);
    gather_kernel<<<blocks, 256>>>(fx, fy, idx, out);
}